// round 11
// baseline (speedup 1.0000x reference)
#include <cuda_runtime.h>
#include <cuda_fp16.h>
#include <cuda_fp8.h>
#include <cstdint>

// Problem constants (fixed by the reference)
#define T_DIM   8192
#define IN_DIM  4096
#define OUT_DIM 4096
#define RANK    32
#define GS      64
#define G_CNT   64
#define TILE_M  128
#define TILE_N  256
#define MT_CNT  (T_DIM / TILE_M)    // 64
#define NT_CNT  (OUT_DIM / TILE_N)  // 16
#define A_CHUNK_BYTES 8192          // 128 rows * 64 B (one group, fp8)
#define B_CHUNK_BYTES 16384         // 256 cols * 64 B
#define STAGE_BYTES   24576
#define NSTAGE  4
#define DSMEM_BYTES (NSTAGE * STAGE_BYTES)   // 96 KB
#define KSPLIT  16

// ---------------------------------------------------------------------------
// Device-global scratch (allocation-free per harness rules)
// Packed fp8 operands, chunk-contiguous, 64B rows swizzled by ((row>>1)&3):
//   g_Apk8[mt][g][row 0..127][64 B]   (q as e4m3, exact ints)
//   g_Bpk8[nt][g][col 0..255][64 B]   (qweight as e4m3, exact ints)
// ---------------------------------------------------------------------------
__device__ __align__(128) uint8_t g_Apk8[(size_t)MT_CNT * G_CNT * A_CHUNK_BYTES];
__device__ __align__(128) uint8_t g_Bpk8[(size_t)NT_CNT * G_CNT * B_CHUNK_BYTES];
__device__ __align__(128) float  g_AscaleT[(size_t)G_CNT * T_DIM];   // [g][t]
__device__ __align__(128) __half g_xsf16[(size_t)T_DIM * IN_DIM];    // smoothed acts
__device__ __align__(128) float  g_lapart[KSPLIT][(size_t)T_DIM * RANK];
__device__ __align__(128) __half g_laf16[(size_t)T_DIM * RANK];      // lora_act fp16
__device__ __align__(128) __half g_puf16[(size_t)OUT_DIM * RANK];    // proj_up fp16
__device__ __align__(128) __half g_pdT[(size_t)RANK * IN_DIM];       // proj_down^T

// ---------------------------------------------------------------------------
// Helpers (sm_90-level features only)
// ---------------------------------------------------------------------------
__device__ __forceinline__ uint32_t smem_to_u32(const void* p) {
    uint32_t a;
    asm("{ .reg .u64 t; cvta.to.shared.u64 t, %1; cvt.u32.u64 %0, t; }"
        : "=r"(a) : "l"(p));
    return a;
}

__device__ __forceinline__ uint32_t elect_one_pred() {
    uint32_t pred;
    asm volatile(
        "{\n\t.reg .pred p;\n\telect.sync _|p, 0xFFFFFFFF;\n\t"
        "selp.b32 %0, 1, 0, p;\n\t}"
        : "=r"(pred));
    return pred;
}

#define MBARRIER_INIT(mbar, count) \
    asm volatile("mbarrier.init.shared.b64 [%0], %1;" \
        :: "r"((uint32_t)(mbar)), "r"((uint32_t)(count)) : "memory")

#define MBARRIER_INVAL(mbar) \
    asm volatile("mbarrier.inval.shared.b64 [%0];" \
        :: "r"((uint32_t)(mbar)) : "memory")

#define MBARRIER_EXPECT_TX(mbar, bytes) \
    asm volatile("mbarrier.arrive.expect_tx.shared.b64 _, [%0], %1;" \
        :: "r"((uint32_t)(mbar)), "r"((uint32_t)(bytes)) : "memory")

#define MBARRIER_WAIT_PARITY(mbar, parity) do { \
    uint32_t _mbar = (uint32_t)(mbar); \
    uint32_t _par  = (uint32_t)(parity); \
    uint32_t _done; \
    asm volatile( \
        "{\n\t.reg .pred p;\n\t" \
        "mbarrier.try_wait.parity.acquire.cta.shared::cta.b64 p, [%1], %2;\n\t" \
        "selp.b32 %0, 1, 0, p;\n\t}" \
        : "=r"(_done) : "r"(_mbar), "r"(_par) : "memory"); \
    if (!_done) { \
        asm volatile( \
            "{\n\t.reg .pred P1;\n\t" \
            "WAIT_LOOP_%=:\n\t" \
            "mbarrier.try_wait.parity.acquire.cta.shared::cta.b64 P1, [%0], %1, 0x989680;\n\t" \
            "@P1 bra.uni WAIT_DONE_%=;\n\t" \
            "bra.uni WAIT_LOOP_%=;\n\t" \
            "WAIT_DONE_%=:\n\t}" \
            :: "r"(_mbar), "r"(_par) : "memory"); \
    } \
} while (0)

#define FENCE_PROXY_ASYNC() \
    asm volatile("fence.proxy.async.shared::cta;" ::: "memory")

#define CP_ASYNC_BULK(dst_smem, src_gmem, bytes, mbar) \
    asm volatile( \
        "cp.async.bulk.shared::cluster.global.mbarrier::complete_tx::bytes " \
        "[%0], [%1], %2, [%3];" \
        :: "r"((uint32_t)(dst_smem)), "l"(src_gmem), "r"((uint32_t)(bytes)), \
           "r"((uint32_t)(mbar)) : "memory")

__device__ __forceinline__ void ldsm4(uint32_t addr, uint32_t f[4]) {
    asm volatile("ldmatrix.sync.aligned.m8n8.x4.shared.b16 {%0,%1,%2,%3}, [%4];"
                 : "=r"(f[0]), "=r"(f[1]), "=r"(f[2]), "=r"(f[3]) : "r"(addr));
}

// 64B-row swizzle (proven in round 8): 16B chunk c XOR ((row>>1)&3)
__device__ __forceinline__ uint32_t swz64(uint32_t base, int row, int chunk) {
    return base + (uint32_t)(row * 64 + ((chunk ^ ((row >> 1) & 3)) << 4));
}
__device__ __forceinline__ int swzb(int h, int row) {   // byte index within 64B row
    return (((h >> 4) ^ ((row >> 1) & 3)) << 4) | (h & 15);
}

__device__ __forceinline__ uint8_t f2e4m3(float v) {
    __nv_fp8_e4m3 f8 = __nv_fp8_e4m3(v);
    return *(uint8_t*)&f8;
}

// ---------------------------------------------------------------------------
// K1: smooth + per-(token,group) int4 quantization -> exact e4m3 ints into
//     packed A; also smoothed fp16 acts and transposed ascale.
// One warp per (token, group).
// ---------------------------------------------------------------------------
__global__ void k1_quant(const float* __restrict__ x, const float* __restrict__ smooth) {
    int warp = (blockIdx.x * blockDim.x + threadIdx.x) >> 5;
    int lane = threadIdx.x & 31;
    int t = warp >> 6;
    int g = warp & 63;
    int base = g * GS;
    size_t xoff = (size_t)t * IN_DIM + base;

    float xs0 = x[xoff + lane] / smooth[base + lane];
    float xs1 = x[xoff + lane + 32] / smooth[base + lane + 32];

    g_xsf16[xoff + lane]      = __float2half(xs0);
    g_xsf16[xoff + lane + 32] = __float2half(xs1);

    float m = fmaxf(fabsf(xs0), fabsf(xs1));
    #pragma unroll
    for (int o = 16; o > 0; o >>= 1)
        m = fmaxf(m, __shfl_xor_sync(0xffffffffu, m, o));

    float ascale = m / 7.0f;                 // matches reference amax/7.0
    if (ascale == 0.0f) ascale = 1.0f;       // matches jnp.where

    float q0 = fminf(fmaxf(rintf(xs0 / ascale), -8.0f), 7.0f);
    float q1 = fminf(fmaxf(rintf(xs1 / ascale), -8.0f), 7.0f);

    int mt = t >> 7, r = t & 127;
    size_t pkbase = ((size_t)(mt * G_CNT + g) * 128 + r) * 64;
    g_Apk8[pkbase + swzb(lane, r)]      = f2e4m3(q0);   // exact int in e4m3
    g_Apk8[pkbase + swzb(lane + 32, r)] = f2e4m3(q1);
    if (lane == 0) g_AscaleT[(size_t)g * T_DIM + t] = ascale;
}

// ---------------------------------------------------------------------------
// K2: pack int32 weights -> exact e4m3 ints into packed B.
// One thread per 16B output chunk (reads 16 int32 = 64B).
// ---------------------------------------------------------------------------
__global__ void k2_packw(const int* __restrict__ qw) {
    int idx = blockIdx.x * blockDim.x + threadIdx.x;   // over OUT * 256
    int o  = idx >> 8;           // output channel
    int cc = idx & 255;          // 16B chunk within the 4096-wide row
    int c  = cc >> 2;            // group
    int c16 = cc & 3;            // chunk within 64B group row

    const int4* qp = (const int4*)(qw + (size_t)o * IN_DIM + cc * 16);
    uint8_t b[16];
    #pragma unroll
    for (int j = 0; j < 4; j++) {
        int4 v = qp[j];
        b[j * 4 + 0] = f2e4m3((float)v.x);
        b[j * 4 + 1] = f2e4m3((float)v.y);
        b[j * 4 + 2] = f2e4m3((float)v.z);
        b[j * 4 + 3] = f2e4m3((float)v.w);
    }
    int nt = o >> 8, col = o & 255;
    size_t base = ((size_t)(nt * G_CNT + c) * 256 + col) * 64;
    int phys = c16 ^ ((col >> 1) & 3);
    *(uint4*)(g_Bpk8 + base + phys * 16) = *(uint4*)b;
}

// ---------------------------------------------------------------------------
// K2b: proj_up fp16; proj_down^T fp16
// ---------------------------------------------------------------------------
__global__ void k2_convert(const float* __restrict__ pu, const float* __restrict__ pd) {
    int idx = blockIdx.x * blockDim.x + threadIdx.x;   // over IN*RANK = 131072
    g_puf16[idx] = __float2half(pu[idx]);              // OUT*RANK == IN*RANK
    int rr = idx >> 12;
    int k  = idx & 4095;
    g_pdT[(size_t)rr * IN_DIM + k] = __float2half(pd[(size_t)k * RANK + rr]);
}

// ---------------------------------------------------------------------------
// K3: lora partials, split-K x16.
// ---------------------------------------------------------------------------
__global__ void k3_lora() {
    int warp = threadIdx.x >> 5;
    int lane = threadIdx.x & 31;
    int gid = lane >> 2;
    int tig = lane & 3;
    int mblk   = blockIdx.x >> 4;
    int kslice = blockIdx.x & 15;
    int m0 = mblk * 128 + warp * 16;

    float acc[4][4];
    #pragma unroll
    for (int ni = 0; ni < 4; ni++)
        #pragma unroll
        for (int j = 0; j < 4; j++) acc[ni][j] = 0.0f;

    const uint32_t* xsr0 = (const uint32_t*)(g_xsf16 + (size_t)(m0 + gid) * IN_DIM);
    const uint32_t* xsr1 = (const uint32_t*)(g_xsf16 + (size_t)(m0 + gid + 8) * IN_DIM);

    int ks0 = kslice * 16;
    #pragma unroll 4
    for (int ks = ks0; ks < ks0 + 16; ks++) {
        int kb = ks * 8 + tig;
        uint32_t a0 = xsr0[kb];
        uint32_t a1 = xsr1[kb];
        uint32_t a2 = xsr0[kb + 4];
        uint32_t a3 = xsr1[kb + 4];
        #pragma unroll
        for (int ni = 0; ni < 4; ni++) {
            int c = ni * 8 + gid;
            const uint32_t* bp = (const uint32_t*)(g_pdT + (size_t)c * IN_DIM);
            uint32_t b0 = bp[kb];
            uint32_t b1 = bp[kb + 4];
            asm volatile(
                "mma.sync.aligned.m16n8k16.row.col.f32.f16.f16.f32 "
                "{%0,%1,%2,%3},{%4,%5,%6,%7},{%8,%9},{%0,%1,%2,%3};"
                : "+f"(acc[ni][0]), "+f"(acc[ni][1]), "+f"(acc[ni][2]), "+f"(acc[ni][3])
                : "r"(a0), "r"(a1), "r"(a2), "r"(a3), "r"(b0), "r"(b1));
        }
    }

    float* dst = g_lapart[kslice];
    #pragma unroll
    for (int ni = 0; ni < 4; ni++) {
        int col = ni * 8 + tig * 2;
        *(float2*)(dst + (size_t)(m0 + gid) * RANK + col)     = make_float2(acc[ni][0], acc[ni][1]);
        *(float2*)(dst + (size_t)(m0 + gid + 8) * RANK + col) = make_float2(acc[ni][2], acc[ni][3]);
    }
}

// K3b: reduce partials -> lora_act fp16
__global__ void k3b_reduce() {
    int idx = blockIdx.x * blockDim.x + threadIdx.x;   // over T*RANK
    float s = 0.0f;
    #pragma unroll
    for (int i = 0; i < KSPLIT; i++) s += g_lapart[i][idx];
    g_laf16[idx] = __float2half(s);
}

// ---------------------------------------------------------------------------
// K4: exact-fp8 W4A4 GEMM, tile 128x256, 64 groups; per-group fp32 rescale.
// 4-stage cp.async.bulk pipeline (24KB/stage); ldmatrix + mma.m16n8k32.e4m3
// (exact integer group sums in f32); epilogue rank-32 lora via fp16 HMMA.
// ---------------------------------------------------------------------------
__global__ void __launch_bounds__(256, 1)
k4_main(const float* __restrict__ wscales, float* __restrict__ out) {
    extern __shared__ __align__(128) char dsm[];
    __shared__ __align__(8) unsigned long long s_full[NSTAGE];

    int tid  = threadIdx.x;
    int wid  = tid >> 5;
    int lane = tid & 31;
    int gid  = lane >> 2;
    int tig  = lane & 3;
    int wm   = (wid >> 2) * 64;     // 0 or 64
    int wn   = (wid & 3) * 64;      // 0,64,128,192

    uint32_t smem = smem_to_u32(dsm);
    uint32_t mb[NSTAGE];
    #pragma unroll
    for (int s = 0; s < NSTAGE; s++) mb[s] = smem_to_u32(&s_full[s]);

    // block swizzle: 16-mt chunks sweep all 16 nt (B stays L2-resident)
    int bid = blockIdx.x;
    int mt  = ((bid >> 8) << 4) + (bid & 15);
    int nt  = (bid >> 4) & 15;
    int m0 = mt * TILE_M, n0 = nt * TILE_N;

    const uint8_t* gA = g_Apk8 + (size_t)mt * G_CNT * A_CHUNK_BYTES;
    const uint8_t* gB = g_Bpk8 + (size_t)nt * G_CNT * B_CHUNK_BYTES;

    if (tid == 0) {
        #pragma unroll
        for (int s = 0; s < NSTAGE; s++) MBARRIER_INIT(mb[s], 1);
    }
    __syncthreads();

    if (wid == 0 && elect_one_pred()) {
        #pragma unroll
        for (int s = 0; s < NSTAGE; s++) {
            uint32_t sA = smem + s * STAGE_BYTES;
            MBARRIER_EXPECT_TX(mb[s], STAGE_BYTES);
            CP_ASYNC_BULK(sA,                 gA + (size_t)s * A_CHUNK_BYTES, A_CHUNK_BYTES, mb[s]);
            CP_ASYNC_BULK(sA + A_CHUNK_BYTES, gB + (size_t)s * B_CHUNK_BYTES, B_CHUNK_BYTES, mb[s]);
        }
    }

    // ldmatrix lane-dependent address parts (proven round-8 mapping)
    int rA_off = ((lane >> 3) & 1) * 8 + (lane & 7);
    int cA_off = lane >> 4;
    int rB_off = (lane >> 4) * 8 + (lane & 7);
    int cB_off = (lane >> 3) & 1;

    float acc[4][8][4];
    #pragma unroll
    for (int a = 0; a < 4; a++)
        #pragma unroll
        for (int b = 0; b < 8; b++)
            #pragma unroll
            for (int c = 0; c < 4; c++) acc[a][b][c] = 0.0f;

    #pragma unroll 1
    for (int g = 0; g < G_CNT; g++) {
        int s = g & 3;
        uint32_t sA = smem + s * STAGE_BYTES;
        uint32_t sB = sA + A_CHUNK_BYTES;

        MBARRIER_WAIT_PARITY(mb[s], (g >> 2) & 1);

        // scales (L2-hot)
        float aLo[4], aHi[4];
        #pragma unroll
        for (int mi = 0; mi < 4; mi++) {
            const float* p = &g_AscaleT[(size_t)g * T_DIM + m0 + wm + mi * 16 + gid];
            aLo[mi] = __ldg(p);
            aHi[mi] = __ldg(p + 8);
        }
        float2 wsv[4][2];
        #pragma unroll
        for (int p = 0; p < 4; p++)
            #pragma unroll
            for (int q = 0; q < 2; q++)
                wsv[p][q] = __ldg((const float2*)&wscales[
                    (size_t)g * OUT_DIM + n0 + wn + p * 16 + q * 8 + tig * 2]);

        // A fragments: [mi][ks][4]
        uint32_t afr[4][2][4];
        #pragma unroll
        for (int mi = 0; mi < 4; mi++)
            #pragma unroll
            for (int ks = 0; ks < 2; ks++)
                ldsm4(swz64(sA, wm + mi * 16 + rA_off, 2 * ks + cA_off), afr[mi][ks]);

        #pragma unroll
        for (int p = 0; p < 4; p++) {
            uint32_t bfr[2][4];
            #pragma unroll
            for (int ks = 0; ks < 2; ks++)
                ldsm4(swz64(sB, wn + p * 16 + rB_off, 2 * ks + cB_off), bfr[ks]);

            #pragma unroll
            for (int mi = 0; mi < 4; mi++) {
                #pragma unroll
                for (int q = 0; q < 2; q++) {
                    int ni = p * 2 + q;
                    float d0 = 0.f, d1 = 0.f, d2 = 0.f, d3 = 0.f;
                    asm volatile(
                        "mma.sync.aligned.m16n8k32.row.col.f32.e4m3.e4m3.f32 "
                        "{%0,%1,%2,%3},{%4,%5,%6,%7},{%8,%9},{%0,%1,%2,%3};"
                        : "+f"(d0), "+f"(d1), "+f"(d2), "+f"(d3)
                        : "r"(afr[mi][0][0]), "r"(afr[mi][0][1]),
                          "r"(afr[mi][0][2]), "r"(afr[mi][0][3]),
                          "r"(bfr[0][2 * q]), "r"(bfr[0][2 * q + 1]));
                    asm volatile(
                        "mma.sync.aligned.m16n8k32.row.col.f32.e4m3.e4m3.f32 "
                        "{%0,%1,%2,%3},{%4,%5,%6,%7},{%8,%9},{%0,%1,%2,%3};"
                        : "+f"(d0), "+f"(d1), "+f"(d2), "+f"(d3)
                        : "r"(afr[mi][1][0]), "r"(afr[mi][1][1]),
                          "r"(afr[mi][1][2]), "r"(afr[mi][1][3]),
                          "r"(bfr[1][2 * q]), "r"(bfr[1][2 * q + 1]));
                    // exact group sums -> fp32 rescale-accumulate (no I2F!)
                    float w0 = wsv[p][q].x, w1 = wsv[p][q].y;
                    acc[mi][ni][0] = fmaf(d0, aLo[mi] * w0, acc[mi][ni][0]);
                    acc[mi][ni][1] = fmaf(d1, aLo[mi] * w1, acc[mi][ni][1]);
                    acc[mi][ni][2] = fmaf(d2, aHi[mi] * w0, acc[mi][ni][2]);
                    acc[mi][ni][3] = fmaf(d3, aHi[mi] * w1, acc[mi][ni][3]);
                }
            }
        }

        __syncthreads();   // CTA done with stage s -> safe to refill

        int gp = g + NSTAGE;
        if (gp < G_CNT && wid == 0) {
            if (elect_one_pred()) {
                FENCE_PROXY_ASYNC();
                MBARRIER_EXPECT_TX(mb[s], STAGE_BYTES);
                CP_ASYNC_BULK(sA, gA + (size_t)gp * A_CHUNK_BYTES, A_CHUNK_BYTES, mb[s]);
                CP_ASYNC_BULK(sA + A_CHUNK_BYTES, gB + (size_t)gp * B_CHUNK_BYTES, B_CHUNK_BYTES, mb[s]);
            }
        }
    }

    // ---------------- epilogue: fused rank-32 lora via fp16 HMMA ----------------
    __syncthreads();
    {
        // stage lora_act [128 rows x 64B] into stage-0 A region, proj_up
        // [256 rows x 64B] into B region, same 64B-row swizzle
        char* sAe = dsm;
        char* sBe = dsm + A_CHUNK_BYTES;
        int row = tid >> 1;
        int c0  = (tid & 1) * 2;
        const int4* la = (const int4*)g_laf16 + (size_t)(m0 + row) * 4;
        int sw = (row >> 1) & 3;
        *(int4*)(sAe + row * 64 + ((c0 ^ sw) << 4))       = la[c0];
        *(int4*)(sAe + row * 64 + (((c0 + 1) ^ sw) << 4)) = la[c0 + 1];
        int brow = tid;   // 0..255
        const int4* puv = (const int4*)g_puf16 + (size_t)(n0 + brow) * 4;
        int bsw = (brow >> 1) & 3;
        #pragma unroll
        for (int c = 0; c < 4; c++)
            *(int4*)(sBe + brow * 64 + ((c ^ bsw) << 4)) = puv[c];
    }
    __syncthreads();
    {
        uint32_t sA = smem, sB = smem + A_CHUNK_BYTES;
        #pragma unroll
        for (int p = 0; p < 4; p++) {
            uint32_t bh[2][4];
            #pragma unroll
            for (int ks = 0; ks < 2; ks++)
                ldsm4(swz64(sB, wn + p * 16 + rB_off, 2 * ks + cB_off), bh[ks]);
            #pragma unroll
            for (int mi = 0; mi < 4; mi++) {
                uint32_t ah[2][4];
                #pragma unroll
                for (int ks = 0; ks < 2; ks++)
                    ldsm4(swz64(sA, wm + mi * 16 + rA_off, 2 * ks + cA_off), ah[ks]);
                #pragma unroll
                for (int q = 0; q < 2; q++) {
                    int ni = p * 2 + q;
                    #pragma unroll
                    for (int ks = 0; ks < 2; ks++) {
                        asm volatile(
                            "mma.sync.aligned.m16n8k16.row.col.f32.f16.f16.f32 "
                            "{%0,%1,%2,%3},{%4,%5,%6,%7},{%8,%9},{%0,%1,%2,%3};"
                            : "+f"(acc[mi][ni][0]), "+f"(acc[mi][ni][1]),
                              "+f"(acc[mi][ni][2]), "+f"(acc[mi][ni][3])
                            : "r"(ah[ks][0]), "r"(ah[ks][1]), "r"(ah[ks][2]), "r"(ah[ks][3]),
                              "r"(bh[ks][2 * q]), "r"(bh[ks][2 * q + 1]));
                    }
                }
            }
        }
    }

    // ---------------- store ----------------
    #pragma unroll
    for (int mi = 0; mi < 4; mi++) {
        int r0 = m0 + wm + mi * 16 + gid;
        #pragma unroll
        for (int p = 0; p < 4; p++) {
            #pragma unroll
            for (int q = 0; q < 2; q++) {
                int ni = p * 2 + q;
                int c = n0 + wn + p * 16 + q * 8 + tig * 2;
                *(float2*)(out + (size_t)r0 * OUT_DIM + c) =
                    make_float2(acc[mi][ni][0], acc[mi][ni][1]);
                *(float2*)(out + (size_t)(r0 + 8) * OUT_DIM + c) =
                    make_float2(acc[mi][ni][2], acc[mi][ni][3]);
            }
        }
    }

    __syncthreads();
    if (tid == 0) {
        #pragma unroll
        for (int s = 0; s < NSTAGE; s++) MBARRIER_INVAL(mb[s]);
    }
}

// ---------------------------------------------------------------------------
// kernel_launch
// inputs: x[f32], qweight[i32], wscales[f32], smooth_factor[f32],
//         proj_down[f32], proj_up[f32]; output: f32 [T, OUT]
// ---------------------------------------------------------------------------
extern "C" void kernel_launch(void* const* d_in, const int* in_sizes, int n_in,
                              void* d_out, int out_size) {
    (void)in_sizes; (void)n_in; (void)out_size;
    const float* x         = (const float*)d_in[0];
    const int*   qweight   = (const int*)d_in[1];
    const float* wscales   = (const float*)d_in[2];
    const float* smooth    = (const float*)d_in[3];
    const float* proj_down = (const float*)d_in[4];
    const float* proj_up   = (const float*)d_in[5];
    float* out = (float*)d_out;

    cudaFuncSetAttribute(k4_main, cudaFuncAttributeMaxDynamicSharedMemorySize,
                         DSMEM_BYTES);

    k1_quant<<<(T_DIM * G_CNT) / 8, 256>>>(x, smooth);
    k2_packw<<<(OUT_DIM * 256) / 256, 256>>>(qweight);
    k2_convert<<<(IN_DIM * RANK) / 256, 256>>>(proj_up, proj_down);
    k3_lora<<<(T_DIM / 128) * KSPLIT, 256>>>();
    k3b_reduce<<<(T_DIM * RANK) / 256, 256>>>();
    k4_main<<<MT_CNT * NT_CNT, 256, DSMEM_BYTES>>>(wscales, out);
}

// round 12
// speedup vs baseline: 1.7152x; 1.7152x over previous
#include <cuda_runtime.h>
#include <cuda_fp16.h>
#include <cstdint>

// Problem constants (fixed by the reference)
#define T_DIM   8192
#define IN_DIM  4096
#define OUT_DIM 4096
#define RANK    32
#define GS      64
#define G_CNT   64
#define NCHUNK  65            // 64 main K-chunks + 1 lora chunk (32 lora + 32 zero)
#define TILE_M  128
#define TILE_N  128
#define MT_CNT  (T_DIM / TILE_M)    // 64
#define NT_CNT  (OUT_DIM / TILE_N)  // 32
#define A_CHUNK_H 8192        // 128 rows * 64 halves
#define B_CHUNK_H 8192        // 128 cols * 64 halves
#define A_CHUNK_BYTES 16384
#define B_CHUNK_BYTES 16384
#define STAGE_BYTES 32768
#define NSTAGE  3
#define DSMEM_BYTES (NSTAGE * STAGE_BYTES)   // 96 KB -> 2 CTAs/SM
#define KSPLIT  32

// ---------------------------------------------------------------------------
// Device-global scratch (allocation-free per harness rules)
// Packed, pre-swizzled fp16 operand layouts (128B rows, 16B chunks XOR row&7):
//   g_Apk[mt][chunk][row 0..127][64 halves]
//   g_Bpk[nt][chunk][col 0..127][64 halves]
// ---------------------------------------------------------------------------
__device__ __align__(128) __half g_Apk[(size_t)MT_CNT * NCHUNK * A_CHUNK_H];
__device__ __align__(128) __half g_Bpk[(size_t)NT_CNT * NCHUNK * B_CHUNK_H];
__device__ __align__(128) __half g_xsf16[(size_t)T_DIM * IN_DIM];   // smoothed acts (lora)
__device__ __align__(128) float  g_lapart[KSPLIT][(size_t)T_DIM * RANK];
__device__ __align__(128) __half g_pdT[(size_t)RANK * IN_DIM];      // proj_down^T fp16

// ---------------------------------------------------------------------------
// Helpers (sm_90-level features only: mbarrier + cp.async.bulk + mma.sync)
// ---------------------------------------------------------------------------
__device__ __forceinline__ uint32_t smem_to_u32(const void* p) {
    uint32_t a;
    asm("{ .reg .u64 t; cvta.to.shared.u64 t, %1; cvt.u32.u64 %0, t; }"
        : "=r"(a) : "l"(p));
    return a;
}

__device__ __forceinline__ uint32_t elect_one_pred() {
    uint32_t pred;
    asm volatile(
        "{\n\t.reg .pred p;\n\telect.sync _|p, 0xFFFFFFFF;\n\t"
        "selp.b32 %0, 1, 0, p;\n\t}"
        : "=r"(pred));
    return pred;
}

#define MBARRIER_INIT(mbar, count) \
    asm volatile("mbarrier.init.shared.b64 [%0], %1;" \
        :: "r"((uint32_t)(mbar)), "r"((uint32_t)(count)) : "memory")

#define MBARRIER_INVAL(mbar) \
    asm volatile("mbarrier.inval.shared.b64 [%0];" \
        :: "r"((uint32_t)(mbar)) : "memory")

#define MBARRIER_EXPECT_TX(mbar, bytes) \
    asm volatile("mbarrier.arrive.expect_tx.shared.b64 _, [%0], %1;" \
        :: "r"((uint32_t)(mbar)), "r"((uint32_t)(bytes)) : "memory")

#define MBARRIER_WAIT_PARITY(mbar, parity) do { \
    uint32_t _mbar = (uint32_t)(mbar); \
    uint32_t _par  = (uint32_t)(parity); \
    uint32_t _done; \
    asm volatile( \
        "{\n\t.reg .pred p;\n\t" \
        "mbarrier.try_wait.parity.acquire.cta.shared::cta.b64 p, [%1], %2;\n\t" \
        "selp.b32 %0, 1, 0, p;\n\t}" \
        : "=r"(_done) : "r"(_mbar), "r"(_par) : "memory"); \
    if (!_done) { \
        asm volatile( \
            "{\n\t.reg .pred P1;\n\t" \
            "WAIT_LOOP_%=:\n\t" \
            "mbarrier.try_wait.parity.acquire.cta.shared::cta.b64 P1, [%0], %1, 0x989680;\n\t" \
            "@P1 bra.uni WAIT_DONE_%=;\n\t" \
            "bra.uni WAIT_LOOP_%=;\n\t" \
            "WAIT_DONE_%=:\n\t}" \
            :: "r"(_mbar), "r"(_par) : "memory"); \
    } \
} while (0)

#define FENCE_PROXY_ASYNC() \
    asm volatile("fence.proxy.async.shared::cta;" ::: "memory")

// 1-D bulk copy GMEM -> SMEM with mbarrier transaction completion (SASS: UBLKCP)
#define CP_ASYNC_BULK(dst_smem, src_gmem, bytes, mbar) \
    asm volatile( \
        "cp.async.bulk.shared::cluster.global.mbarrier::complete_tx::bytes " \
        "[%0], [%1], %2, [%3];" \
        :: "r"((uint32_t)(dst_smem)), "l"(src_gmem), "r"((uint32_t)(bytes)), \
           "r"((uint32_t)(mbar)) : "memory")

__device__ __forceinline__ void ldsm4(uint32_t addr, uint32_t f[4]) {
    asm volatile("ldmatrix.sync.aligned.m8n8.x4.shared.b16 {%0,%1,%2,%3}, [%4];"
                 : "=r"(f[0]), "=r"(f[1]), "=r"(f[2]), "=r"(f[3]) : "r"(addr));
}

// swizzled half-index within a 64-half (128B) row: 16B chunk XOR (row&7)
__device__ __forceinline__ int swz_h(int h, int r) {
    return (((h >> 3) ^ (r & 7)) << 3) | (h & 7);
}

// ---------------------------------------------------------------------------
// K1: smooth + per-(token,group) int4 quantization; writes xdq fp16 directly
//     into the packed+swizzled A layout, plus smoothed fp16 acts for lora.
// One warp per (token, group).
// ---------------------------------------------------------------------------
__global__ void k1_quant(const float* __restrict__ x, const float* __restrict__ smooth) {
    int warp = (blockIdx.x * blockDim.x + threadIdx.x) >> 5;
    int lane = threadIdx.x & 31;
    int t = warp >> 6;
    int g = warp & 63;
    int base = g * GS;
    size_t xoff = (size_t)t * IN_DIM + base;

    float xs0 = x[xoff + lane] / smooth[base + lane];
    float xs1 = x[xoff + lane + 32] / smooth[base + lane + 32];

    g_xsf16[xoff + lane]      = __float2half(xs0);
    g_xsf16[xoff + lane + 32] = __float2half(xs1);

    float m = fmaxf(fabsf(xs0), fabsf(xs1));
    #pragma unroll
    for (int o = 16; o > 0; o >>= 1)
        m = fmaxf(m, __shfl_xor_sync(0xffffffffu, m, o));

    float ascale = m / 7.0f;                 // matches reference amax/7.0
    if (ascale == 0.0f) ascale = 1.0f;       // matches jnp.where

    float q0 = fminf(fmaxf(rintf(xs0 / ascale), -8.0f), 7.0f);
    float q1 = fminf(fmaxf(rintf(xs1 / ascale), -8.0f), 7.0f);

    int mt = t >> 7, r = t & 127;
    size_t pkbase = ((size_t)(mt * NCHUNK + g) * 128 + r) * 64;
    g_Apk[pkbase + swz_h(lane, r)]      = __float2half(q0 * ascale);
    g_Apk[pkbase + swz_h(lane + 32, r)] = __float2half(q1 * ascale);
}

// ---------------------------------------------------------------------------
// K2: dequantize weights into packed+swizzled B: wdq = qw * wscale[g][o]
// One thread per 16B output chunk (8 halves).  idx over OUT*512.
// ---------------------------------------------------------------------------
__global__ void k2_wdq(const int* __restrict__ qw, const float* __restrict__ wscales) {
    int idx = blockIdx.x * blockDim.x + threadIdx.x;
    int o   = idx >> 9;          // output channel
    int rem = idx & 511;
    int c   = rem >> 3;          // group / chunk
    int c16 = rem & 7;           // 16B chunk within 128B row
    float ws = __ldg(&wscales[(size_t)c * OUT_DIM + o]);

    int k = c * 64 + c16 * 8;
    const int4* qp = (const int4*)(qw + (size_t)o * IN_DIM + k);
    int4 v0 = qp[0], v1 = qp[1];
    __half2 p0 = __floats2half2_rn((float)v0.x * ws, (float)v0.y * ws);
    __half2 p1 = __floats2half2_rn((float)v0.z * ws, (float)v0.w * ws);
    __half2 p2 = __floats2half2_rn((float)v1.x * ws, (float)v1.y * ws);
    __half2 p3 = __floats2half2_rn((float)v1.z * ws, (float)v1.w * ws);
    uint4 w;
    w.x = *(uint32_t*)&p0; w.y = *(uint32_t*)&p1;
    w.z = *(uint32_t*)&p2; w.w = *(uint32_t*)&p3;

    int nt = o >> 7, col = o & 127;
    size_t base = ((size_t)(nt * NCHUNK + c) * 128 + col) * 64;
    int phys16 = c16 ^ (col & 7);
    *(uint4*)(g_Bpk + base + phys16 * 8) = w;
}

// ---------------------------------------------------------------------------
// K2b: proj_down^T fp16; B lora chunk (proj_up fp16 + zero pad).
// idx over IN*RANK = 131072; first 32768 also write one 16B B-tail chunk.
// ---------------------------------------------------------------------------
__global__ void k2_convert(const float* __restrict__ pu, const float* __restrict__ pd) {
    int idx = blockIdx.x * blockDim.x + threadIdx.x;
    int rr = idx >> 12;
    int k  = idx & 4095;
    g_pdT[(size_t)rr * IN_DIM + k] = __float2half(pd[(size_t)k * RANK + rr]);

    if (idx < OUT_DIM * 8) {
        int o = idx >> 3, c16 = idx & 7;
        uint4 w;
        if (c16 < 4) {
            const float* src = pu + (size_t)o * RANK + c16 * 8;
            __half2 p0 = __floats2half2_rn(src[0], src[1]);
            __half2 p1 = __floats2half2_rn(src[2], src[3]);
            __half2 p2 = __floats2half2_rn(src[4], src[5]);
            __half2 p3 = __floats2half2_rn(src[6], src[7]);
            w.x = *(uint32_t*)&p0; w.y = *(uint32_t*)&p1;
            w.z = *(uint32_t*)&p2; w.w = *(uint32_t*)&p3;
        } else {
            w = make_uint4(0, 0, 0, 0);
        }
        int nt = o >> 7, col = o & 127;
        size_t base = ((size_t)(nt * NCHUNK + 64) * 128 + col) * 64;
        int phys16 = c16 ^ (col & 7);
        *(uint4*)(g_Bpk + base + phys16 * 8) = w;
    }
}

// ---------------------------------------------------------------------------
// K3: lora partials, split-K x32 (latency-bound -> more blocks).
// ---------------------------------------------------------------------------
__global__ void k3_lora() {
    int warp = threadIdx.x >> 5;
    int lane = threadIdx.x & 31;
    int gid = lane >> 2;
    int tig = lane & 3;
    int mblk   = blockIdx.x >> 5;
    int kslice = blockIdx.x & 31;
    int m0 = mblk * 128 + warp * 16;

    float acc[4][4];
    #pragma unroll
    for (int ni = 0; ni < 4; ni++)
        #pragma unroll
        for (int j = 0; j < 4; j++) acc[ni][j] = 0.0f;

    const uint32_t* xsr0 = (const uint32_t*)(g_xsf16 + (size_t)(m0 + gid) * IN_DIM);
    const uint32_t* xsr1 = (const uint32_t*)(g_xsf16 + (size_t)(m0 + gid + 8) * IN_DIM);

    int ks0 = kslice * 8;
    #pragma unroll
    for (int ks = ks0; ks < ks0 + 8; ks++) {
        int kb = ks * 8 + tig;
        uint32_t a0 = xsr0[kb];
        uint32_t a1 = xsr1[kb];
        uint32_t a2 = xsr0[kb + 4];
        uint32_t a3 = xsr1[kb + 4];
        #pragma unroll
        for (int ni = 0; ni < 4; ni++) {
            int c = ni * 8 + gid;
            const uint32_t* bp = (const uint32_t*)(g_pdT + (size_t)c * IN_DIM);
            uint32_t b0 = bp[kb];
            uint32_t b1 = bp[kb + 4];
            asm volatile(
                "mma.sync.aligned.m16n8k16.row.col.f32.f16.f16.f32 "
                "{%0,%1,%2,%3},{%4,%5,%6,%7},{%8,%9},{%0,%1,%2,%3};"
                : "+f"(acc[ni][0]), "+f"(acc[ni][1]), "+f"(acc[ni][2]), "+f"(acc[ni][3])
                : "r"(a0), "r"(a1), "r"(a2), "r"(a3), "r"(b0), "r"(b1));
        }
    }

    float* dst = g_lapart[kslice];
    #pragma unroll
    for (int ni = 0; ni < 4; ni++) {
        int col = ni * 8 + tig * 2;
        *(float2*)(dst + (size_t)(m0 + gid) * RANK + col)     = make_float2(acc[ni][0], acc[ni][1]);
        *(float2*)(dst + (size_t)(m0 + gid + 8) * RANK + col) = make_float2(acc[ni][2], acc[ni][3]);
    }
}

// K3b: reduce partials -> A lora chunk (fp16) + zero pad
__global__ void k3b_reduce() {
    int idx = blockIdx.x * blockDim.x + threadIdx.x;   // over T*RANK
    float s = 0.0f;
    #pragma unroll
    for (int i = 0; i < KSPLIT; i++) s += g_lapart[i][idx];
    int t = idx >> 5, rk = idx & 31;
    int mt = t >> 7, r = t & 127;
    size_t base = ((size_t)(mt * NCHUNK + 64) * 128 + r) * 64;
    g_Apk[base + swz_h(rk, r)]      = __float2half(s);
    g_Apk[base + swz_h(rk + 32, r)] = __float2half(0.0f);
}

// ---------------------------------------------------------------------------
// K4: fp16 HMMA GEMM, tile 128x128, 65 K-chunks of 64 halves, 2 CTAs/SM.
// 3-stage cp.async.bulk pipeline (32KB/stage); ldmatrix + mma.m16n8k16.
// ---------------------------------------------------------------------------
__global__ void __launch_bounds__(256, 2)
k4_main(float* __restrict__ out) {
    extern __shared__ __align__(128) char dsm[];
    __shared__ __align__(8) unsigned long long s_full[NSTAGE];

    int tid  = threadIdx.x;
    int wid  = tid >> 5;
    int lane = tid & 31;
    int gid  = lane >> 2;
    int tig  = lane & 3;
    int wm   = (wid >> 2) * 64;     // warp row offset: 0 or 64
    int wn   = (wid & 3) * 32;      // warp col offset: 0,32,64,96

    uint32_t smem = smem_to_u32(dsm);
    uint32_t mb[NSTAGE];
    #pragma unroll
    for (int s = 0; s < NSTAGE; s++) mb[s] = smem_to_u32(&s_full[s]);

    // L2-friendly swizzle: 16-mt chunks sweep all 32 nt (~50MB working set)
    int bid = blockIdx.x;                     // 0..2047
    int mt  = ((bid >> 9) << 4) + (bid & 15); // 0..63
    int nt  = (bid >> 4) & 31;                // 0..31
    int m0 = mt * TILE_M, n0 = nt * TILE_N;

    const __half* gA = g_Apk + (size_t)mt * NCHUNK * A_CHUNK_H;
    const __half* gB = g_Bpk + (size_t)nt * NCHUNK * B_CHUNK_H;

    if (tid == 0) {
        #pragma unroll
        for (int s = 0; s < NSTAGE; s++) MBARRIER_INIT(mb[s], 1);
    }
    __syncthreads();

    // prologue: fill all 3 stages (chunks 0..2)
    if (wid == 0 && elect_one_pred()) {
        #pragma unroll
        for (int s = 0; s < NSTAGE; s++) {
            uint32_t sA = smem + s * STAGE_BYTES;
            MBARRIER_EXPECT_TX(mb[s], STAGE_BYTES);
            CP_ASYNC_BULK(sA,                 gA + (size_t)s * A_CHUNK_H, A_CHUNK_BYTES, mb[s]);
            CP_ASYNC_BULK(sA + A_CHUNK_BYTES, gB + (size_t)s * B_CHUNK_H, B_CHUNK_BYTES, mb[s]);
        }
    }

    // ldmatrix lane-dependent address parts (proven round-8/10 mapping)
    int rA_off = ((lane >> 3) & 1) * 8 + (lane & 7);
    int cA_off = lane >> 4;           // 0/1
    int rB_off = (lane >> 4) * 8 + (lane & 7);
    int cB_off = (lane >> 3) & 1;     // 0/1

    uint32_t aRow[4], aXor[4], bRow[2], bXor[2];
    #pragma unroll
    for (int mi = 0; mi < 4; mi++) {
        int r = wm + mi * 16 + rA_off;
        aRow[mi] = (uint32_t)(r * 128);
        aXor[mi] = (uint32_t)((r & 7) << 4);
    }
    #pragma unroll
    for (int nb = 0; nb < 2; nb++) {
        int c = wn + nb * 16 + rB_off;
        bRow[nb] = (uint32_t)(c * 128);
        bXor[nb] = (uint32_t)((c & 7) << 4);
    }

    float acc[4][4][4];
    #pragma unroll
    for (int a = 0; a < 4; a++)
        #pragma unroll
        for (int b = 0; b < 4; b++)
            #pragma unroll
            for (int c = 0; c < 4; c++) acc[a][b][c] = 0.0f;

    int st = 0, ph = 0;
    #pragma unroll 1
    for (int g = 0; g < NCHUNK; g++) {
        uint32_t sA = smem + st * STAGE_BYTES;
        uint32_t sB = sA + A_CHUNK_BYTES;

        MBARRIER_WAIT_PARITY(mb[st], ph);

        #pragma unroll
        for (int ks = 0; ks < 4; ks++) {
            uint32_t cA16 = (uint32_t)((2 * ks + cA_off) << 4);
            uint32_t cB16 = (uint32_t)((2 * ks + cB_off) << 4);

            uint32_t bfr[2][4];
            #pragma unroll
            for (int nb = 0; nb < 2; nb++)
                ldsm4(sB + bRow[nb] + (cB16 ^ bXor[nb]), bfr[nb]);

            uint32_t afr[4][4];
            #pragma unroll
            for (int mi = 0; mi < 4; mi++)
                ldsm4(sA + aRow[mi] + (cA16 ^ aXor[mi]), afr[mi]);

            #pragma unroll
            for (int mi = 0; mi < 4; mi++) {
                #pragma unroll
                for (int nb = 0; nb < 2; nb++) {
                    #pragma unroll
                    for (int q = 0; q < 2; q++) {
                        int ni = nb * 2 + q;
                        asm volatile(
                            "mma.sync.aligned.m16n8k16.row.col.f32.f16.f16.f32 "
                            "{%0,%1,%2,%3},{%4,%5,%6,%7},{%8,%9},{%0,%1,%2,%3};"
                            : "+f"(acc[mi][ni][0]), "+f"(acc[mi][ni][1]),
                              "+f"(acc[mi][ni][2]), "+f"(acc[mi][ni][3])
                            : "r"(afr[mi][0]), "r"(afr[mi][1]),
                              "r"(afr[mi][2]), "r"(afr[mi][3]),
                              "r"(bfr[nb][2 * q]), "r"(bfr[nb][2 * q + 1]));
                    }
                }
            }
        }

        __syncthreads();   // whole CTA done with stage st -> safe to refill

        int gp = g + NSTAGE;
        if (gp < NCHUNK && wid == 0) {
            if (elect_one_pred()) {
                FENCE_PROXY_ASYNC();
                MBARRIER_EXPECT_TX(mb[st], STAGE_BYTES);
                CP_ASYNC_BULK(sA, gA + (size_t)gp * A_CHUNK_H, A_CHUNK_BYTES, mb[st]);
                CP_ASYNC_BULK(sB, gB + (size_t)gp * B_CHUNK_H, B_CHUNK_BYTES, mb[st]);
            }
        }

        if (++st == NSTAGE) { st = 0; ph ^= 1; }
    }

    // ---------------- store ----------------
    #pragma unroll
    for (int mi = 0; mi < 4; mi++) {
        int r0 = m0 + wm + mi * 16 + gid;
        #pragma unroll
        for (int nb = 0; nb < 2; nb++) {
            #pragma unroll
            for (int q = 0; q < 2; q++) {
                int ni = nb * 2 + q;
                int c = n0 + wn + nb * 16 + q * 8 + tig * 2;
                *(float2*)(out + (size_t)r0 * OUT_DIM + c) =
                    make_float2(acc[mi][ni][0], acc[mi][ni][1]);
                *(float2*)(out + (size_t)(r0 + 8) * OUT_DIM + c) =
                    make_float2(acc[mi][ni][2], acc[mi][ni][3]);
            }
        }
    }

    __syncthreads();
    if (tid == 0) {
        #pragma unroll
        for (int s = 0; s < NSTAGE; s++) MBARRIER_INVAL(mb[s]);
    }
}

// ---------------------------------------------------------------------------
// kernel_launch
// inputs: x[f32], qweight[i32], wscales[f32], smooth_factor[f32],
//         proj_down[f32], proj_up[f32]; output: f32 [T, OUT]
// ---------------------------------------------------------------------------
extern "C" void kernel_launch(void* const* d_in, const int* in_sizes, int n_in,
                              void* d_out, int out_size) {
    (void)in_sizes; (void)n_in; (void)out_size;
    const float* x         = (const float*)d_in[0];
    const int*   qweight   = (const int*)d_in[1];
    const float* wscales   = (const float*)d_in[2];
    const float* smooth    = (const float*)d_in[3];
    const float* proj_down = (const float*)d_in[4];
    const float* proj_up   = (const float*)d_in[5];
    float* out = (float*)d_out;

    cudaFuncSetAttribute(k4_main, cudaFuncAttributeMaxDynamicSharedMemorySize,
                         DSMEM_BYTES);

    k1_quant<<<(T_DIM * G_CNT) / 8, 256>>>(x, smooth);
    k2_wdq<<<(OUT_DIM * 512) / 256, 256>>>(qweight, wscales);
    k2_convert<<<(IN_DIM * RANK) / 256, 256>>>(proj_up, proj_down);
    k3_lora<<<(T_DIM / 128) * KSPLIT, 256>>>();
    k3b_reduce<<<(T_DIM * RANK) / 256, 256>>>();
    k4_main<<<MT_CNT * NT_CNT, 256, DSMEM_BYTES>>>(out);
}

// round 13
// speedup vs baseline: 1.8178x; 1.0599x over previous
#include <cuda_runtime.h>
#include <cuda_fp16.h>
#include <cstdint>

// Problem constants (fixed by the reference)
#define T_DIM   8192
#define IN_DIM  4096
#define OUT_DIM 4096
#define RANK    32
#define GS      64
#define G_CNT   64
#define NCHUNK  65            // 64 main K-chunks + 1 lora chunk (32 lora + 32 zero)
#define TILE_M  128
#define TILE_N  128
#define MT_CNT  (T_DIM / TILE_M)    // 64
#define NT_CNT  (OUT_DIM / TILE_N)  // 32
#define A_CHUNK_H 8192        // 128 rows * 64 halves
#define B_CHUNK_H 8192        // 128 cols * 64 halves
#define A_CHUNK_BYTES 16384
#define B_CHUNK_BYTES 16384
#define STAGE_BYTES 32768
#define NSTAGE  3
#define DSMEM_BYTES (NSTAGE * STAGE_BYTES)   // 96 KB -> 2 CTAs/SM
#define KSPLIT  16
#define K3_KS   256           // k-span per k3 block

// ---------------------------------------------------------------------------
// Device-global scratch (allocation-free per harness rules)
// Packed, pre-swizzled fp16 operand layouts (128B rows, 16B chunks XOR row&7):
//   g_Apk[mt][chunk][row 0..127][64 halves]
//   g_Bpk[nt][chunk][col 0..127][64 halves]
// ---------------------------------------------------------------------------
__device__ __align__(128) __half g_Apk[(size_t)MT_CNT * NCHUNK * A_CHUNK_H];
__device__ __align__(128) __half g_Bpk[(size_t)NT_CNT * NCHUNK * B_CHUNK_H];
__device__ __align__(128) __half g_xsf16[(size_t)T_DIM * IN_DIM];   // smoothed acts (lora)
__device__ __align__(128) float  g_lapart[KSPLIT][(size_t)T_DIM * RANK];
__device__ __align__(128) __half g_pdT[(size_t)RANK * IN_DIM];      // proj_down^T fp16

// ---------------------------------------------------------------------------
// Helpers (sm_90-level features only: mbarrier + cp.async.bulk + mma.sync)
// ---------------------------------------------------------------------------
__device__ __forceinline__ uint32_t smem_to_u32(const void* p) {
    uint32_t a;
    asm("{ .reg .u64 t; cvta.to.shared.u64 t, %1; cvt.u32.u64 %0, t; }"
        : "=r"(a) : "l"(p));
    return a;
}

__device__ __forceinline__ uint32_t elect_one_pred() {
    uint32_t pred;
    asm volatile(
        "{\n\t.reg .pred p;\n\telect.sync _|p, 0xFFFFFFFF;\n\t"
        "selp.b32 %0, 1, 0, p;\n\t}"
        : "=r"(pred));
    return pred;
}

#define MBARRIER_INIT(mbar, count) \
    asm volatile("mbarrier.init.shared.b64 [%0], %1;" \
        :: "r"((uint32_t)(mbar)), "r"((uint32_t)(count)) : "memory")

#define MBARRIER_INVAL(mbar) \
    asm volatile("mbarrier.inval.shared.b64 [%0];" \
        :: "r"((uint32_t)(mbar)) : "memory")

#define MBARRIER_EXPECT_TX(mbar, bytes) \
    asm volatile("mbarrier.arrive.expect_tx.shared.b64 _, [%0], %1;" \
        :: "r"((uint32_t)(mbar)), "r"((uint32_t)(bytes)) : "memory")

#define MBARRIER_ARRIVE(mbar) \
    asm volatile("mbarrier.arrive.shared.b64 _, [%0];" \
        :: "r"((uint32_t)(mbar)) : "memory")

#define MBARRIER_WAIT_PARITY(mbar, parity) do { \
    uint32_t _mbar = (uint32_t)(mbar); \
    uint32_t _par  = (uint32_t)(parity); \
    uint32_t _done; \
    asm volatile( \
        "{\n\t.reg .pred p;\n\t" \
        "mbarrier.try_wait.parity.acquire.cta.shared::cta.b64 p, [%1], %2;\n\t" \
        "selp.b32 %0, 1, 0, p;\n\t}" \
        : "=r"(_done) : "r"(_mbar), "r"(_par) : "memory"); \
    if (!_done) { \
        asm volatile( \
            "{\n\t.reg .pred P1;\n\t" \
            "WAIT_LOOP_%=:\n\t" \
            "mbarrier.try_wait.parity.acquire.cta.shared::cta.b64 P1, [%0], %1, 0x989680;\n\t" \
            "@P1 bra.uni WAIT_DONE_%=;\n\t" \
            "bra.uni WAIT_LOOP_%=;\n\t" \
            "WAIT_DONE_%=:\n\t}" \
            :: "r"(_mbar), "r"(_par) : "memory"); \
    } \
} while (0)

#define FENCE_PROXY_ASYNC() \
    asm volatile("fence.proxy.async.shared::cta;" ::: "memory")

// 1-D bulk copy GMEM -> SMEM with mbarrier transaction completion (SASS: UBLKCP)
#define CP_ASYNC_BULK(dst_smem, src_gmem, bytes, mbar) \
    asm volatile( \
        "cp.async.bulk.shared::cluster.global.mbarrier::complete_tx::bytes " \
        "[%0], [%1], %2, [%3];" \
        :: "r"((uint32_t)(dst_smem)), "l"(src_gmem), "r"((uint32_t)(bytes)), \
           "r"((uint32_t)(mbar)) : "memory")

__device__ __forceinline__ void ldsm4(uint32_t addr, uint32_t f[4]) {
    asm volatile("ldmatrix.sync.aligned.m8n8.x4.shared.b16 {%0,%1,%2,%3}, [%4];"
                 : "=r"(f[0]), "=r"(f[1]), "=r"(f[2]), "=r"(f[3]) : "r"(addr));
}

// swizzled half-index within a 64-half (128B) row: 16B chunk XOR (row&7)
__device__ __forceinline__ int swz_h(int h, int r) {
    return (((h >> 3) ^ (r & 7)) << 3) | (h & 7);
}

// ---------------------------------------------------------------------------
// K1: smooth + per-(token,group) int4 quantization; writes xdq fp16 directly
//     into the packed+swizzled A layout, plus smoothed fp16 acts for lora.
// One warp per (token, group).
// ---------------------------------------------------------------------------
__global__ void k1_quant(const float* __restrict__ x, const float* __restrict__ smooth) {
    int warp = (blockIdx.x * blockDim.x + threadIdx.x) >> 5;
    int lane = threadIdx.x & 31;
    int t = warp >> 6;
    int g = warp & 63;
    int base = g * GS;
    size_t xoff = (size_t)t * IN_DIM + base;

    float xs0 = x[xoff + lane] / smooth[base + lane];
    float xs1 = x[xoff + lane + 32] / smooth[base + lane + 32];

    g_xsf16[xoff + lane]      = __float2half(xs0);
    g_xsf16[xoff + lane + 32] = __float2half(xs1);

    float m = fmaxf(fabsf(xs0), fabsf(xs1));
    #pragma unroll
    for (int o = 16; o > 0; o >>= 1)
        m = fmaxf(m, __shfl_xor_sync(0xffffffffu, m, o));

    float ascale = m / 7.0f;                 // matches reference amax/7.0
    if (ascale == 0.0f) ascale = 1.0f;       // matches jnp.where

    float q0 = fminf(fmaxf(rintf(xs0 / ascale), -8.0f), 7.0f);
    float q1 = fminf(fmaxf(rintf(xs1 / ascale), -8.0f), 7.0f);

    int mt = t >> 7, r = t & 127;
    size_t pkbase = ((size_t)(mt * NCHUNK + g) * 128 + r) * 64;
    g_Apk[pkbase + swz_h(lane, r)]      = __float2half(q0 * ascale);
    g_Apk[pkbase + swz_h(lane + 32, r)] = __float2half(q1 * ascale);
}

// ---------------------------------------------------------------------------
// K2: dequantize weights into packed+swizzled B: wdq = qw * wscale[g][o]
// One thread per 16B output chunk (8 halves).  idx over OUT*512.
// ---------------------------------------------------------------------------
__global__ void k2_wdq(const int* __restrict__ qw, const float* __restrict__ wscales) {
    int idx = blockIdx.x * blockDim.x + threadIdx.x;
    int o   = idx >> 9;          // output channel
    int rem = idx & 511;
    int c   = rem >> 3;          // group / chunk
    int c16 = rem & 7;           // 16B chunk within 128B row
    float ws = __ldg(&wscales[(size_t)c * OUT_DIM + o]);

    int k = c * 64 + c16 * 8;
    const int4* qp = (const int4*)(qw + (size_t)o * IN_DIM + k);
    int4 v0 = qp[0], v1 = qp[1];
    __half2 p0 = __floats2half2_rn((float)v0.x * ws, (float)v0.y * ws);
    __half2 p1 = __floats2half2_rn((float)v0.z * ws, (float)v0.w * ws);
    __half2 p2 = __floats2half2_rn((float)v1.x * ws, (float)v1.y * ws);
    __half2 p3 = __floats2half2_rn((float)v1.z * ws, (float)v1.w * ws);
    uint4 w;
    w.x = *(uint32_t*)&p0; w.y = *(uint32_t*)&p1;
    w.z = *(uint32_t*)&p2; w.w = *(uint32_t*)&p3;

    int nt = o >> 7, col = o & 127;
    size_t base = ((size_t)(nt * NCHUNK + c) * 128 + col) * 64;
    int phys16 = c16 ^ (col & 7);
    *(uint4*)(g_Bpk + base + phys16 * 8) = w;
}

// ---------------------------------------------------------------------------
// K2b: proj_down^T fp16; B lora chunk (proj_up fp16 + zero pad).
// idx over IN*RANK = 131072; first 32768 also write one 16B B-tail chunk.
// ---------------------------------------------------------------------------
__global__ void k2_convert(const float* __restrict__ pu, const float* __restrict__ pd) {
    int idx = blockIdx.x * blockDim.x + threadIdx.x;
    int rr = idx >> 12;
    int k  = idx & 4095;
    g_pdT[(size_t)rr * IN_DIM + k] = __float2half(pd[(size_t)k * RANK + rr]);

    if (idx < OUT_DIM * 8) {
        int o = idx >> 3, c16 = idx & 7;
        uint4 w;
        if (c16 < 4) {
            const float* src = pu + (size_t)o * RANK + c16 * 8;
            __half2 p0 = __floats2half2_rn(src[0], src[1]);
            __half2 p1 = __floats2half2_rn(src[2], src[3]);
            __half2 p2 = __floats2half2_rn(src[4], src[5]);
            __half2 p3 = __floats2half2_rn(src[6], src[7]);
            w.x = *(uint32_t*)&p0; w.y = *(uint32_t*)&p1;
            w.z = *(uint32_t*)&p2; w.w = *(uint32_t*)&p3;
        } else {
            w = make_uint4(0, 0, 0, 0);
        }
        int nt = o >> 7, col = o & 127;
        size_t base = ((size_t)(nt * NCHUNK + 64) * 128 + col) * 64;
        int phys16 = c16 ^ (col & 7);
        *(uint4*)(g_Bpk + base + phys16 * 8) = w;
    }
}

// ---------------------------------------------------------------------------
// K3: lora partials, split-K x16, pdT slice staged in smem (kills the L1
// wavefront bottleneck seen in ncu: 81% L1 from repeated global B loads).
// ---------------------------------------------------------------------------
#define PD_STRIDE 264   // halves; 132 words -> conflict-free across c (gid) lanes
__global__ void k3_lora() {
    __shared__ __align__(16) __half s_pd[RANK * PD_STRIDE];

    int tid  = threadIdx.x;
    int warp = tid >> 5;
    int lane = tid & 31;
    int gid  = lane >> 2;
    int tig  = lane & 3;
    int mblk   = blockIdx.x >> 4;    // 0..63
    int kslice = blockIdx.x & 15;    // 0..15
    int m0 = mblk * 128 + warp * 16;
    int k0 = kslice * K3_KS;

    // stage pd^T slice [32 rows x 256 halves] into smem (4x int4 per thread)
    {
        int r   = tid >> 3;          // 0..31
        int seg = (tid & 7) * 32;    // halves
        const int4* src = (const int4*)(g_pdT + (size_t)r * IN_DIM + k0 + seg);
        int4* dst = (int4*)(s_pd + r * PD_STRIDE + seg);
        #pragma unroll
        for (int j = 0; j < 4; j++) dst[j] = src[j];
    }
    __syncthreads();

    float acc[4][4];
    #pragma unroll
    for (int ni = 0; ni < 4; ni++)
        #pragma unroll
        for (int j = 0; j < 4; j++) acc[ni][j] = 0.0f;

    const uint32_t* xsr0 = (const uint32_t*)(g_xsf16 + (size_t)(m0 + gid) * IN_DIM + k0);
    const uint32_t* xsr1 = (const uint32_t*)(g_xsf16 + (size_t)(m0 + gid + 8) * IN_DIM + k0);

    #pragma unroll 4
    for (int ks = 0; ks < K3_KS / 16; ks++) {
        int kb = ks * 8 + tig;
        uint32_t a0 = xsr0[kb];
        uint32_t a1 = xsr1[kb];
        uint32_t a2 = xsr0[kb + 4];
        uint32_t a3 = xsr1[kb + 4];
        #pragma unroll
        for (int ni = 0; ni < 4; ni++) {
            int c = ni * 8 + gid;
            const __half* bp = s_pd + c * PD_STRIDE + ks * 16;
            uint32_t b0 = *(const uint32_t*)(bp + tig * 2);
            uint32_t b1 = *(const uint32_t*)(bp + 8 + tig * 2);
            asm volatile(
                "mma.sync.aligned.m16n8k16.row.col.f32.f16.f16.f32 "
                "{%0,%1,%2,%3},{%4,%5,%6,%7},{%8,%9},{%0,%1,%2,%3};"
                : "+f"(acc[ni][0]), "+f"(acc[ni][1]), "+f"(acc[ni][2]), "+f"(acc[ni][3])
                : "r"(a0), "r"(a1), "r"(a2), "r"(a3), "r"(b0), "r"(b1));
        }
    }

    float* dst = g_lapart[kslice];
    #pragma unroll
    for (int ni = 0; ni < 4; ni++) {
        int col = ni * 8 + tig * 2;
        *(float2*)(dst + (size_t)(m0 + gid) * RANK + col)     = make_float2(acc[ni][0], acc[ni][1]);
        *(float2*)(dst + (size_t)(m0 + gid + 8) * RANK + col) = make_float2(acc[ni][2], acc[ni][3]);
    }
}

// K3b: reduce partials -> A lora chunk (fp16) + zero pad
__global__ void k3b_reduce() {
    int idx = blockIdx.x * blockDim.x + threadIdx.x;   // over T*RANK
    float s = 0.0f;
    #pragma unroll
    for (int i = 0; i < KSPLIT; i++) s += g_lapart[i][idx];
    int t = idx >> 5, rk = idx & 31;
    int mt = t >> 7, r = t & 127;
    size_t base = ((size_t)(mt * NCHUNK + 64) * 128 + r) * 64;
    g_Apk[base + swz_h(rk, r)]      = __float2half(s);
    g_Apk[base + swz_h(rk + 32, r)] = __float2half(0.0f);
}

// ---------------------------------------------------------------------------
// K4: fp16 HMMA GEMM, tile 128x128, 65 K-chunks, 2 CTAs/SM, 3-stage
// cp.async.bulk pipeline. Per-stage full (tx) + empty (count=8) mbarriers
// replace the per-chunk __syncthreads: warps skew freely, producer refills
// as soon as all 8 warps have consumed a stage.
// ---------------------------------------------------------------------------
__global__ void __launch_bounds__(256, 2)
k4_main(float* __restrict__ out) {
    extern __shared__ __align__(128) char dsm[];
    __shared__ __align__(8) unsigned long long s_full[NSTAGE];
    __shared__ __align__(8) unsigned long long s_empty[NSTAGE];

    int tid  = threadIdx.x;
    int wid  = tid >> 5;
    int lane = tid & 31;
    int gid  = lane >> 2;
    int tig  = lane & 3;
    int wm   = (wid >> 2) * 64;     // warp row offset: 0 or 64
    int wn   = (wid & 3) * 32;      // warp col offset: 0,32,64,96

    uint32_t smem = smem_to_u32(dsm);
    uint32_t mbF[NSTAGE], mbE[NSTAGE];
    #pragma unroll
    for (int s = 0; s < NSTAGE; s++) {
        mbF[s] = smem_to_u32(&s_full[s]);
        mbE[s] = smem_to_u32(&s_empty[s]);
    }

    // L2-friendly swizzle: 16-mt chunks sweep all 32 nt (~50MB working set)
    int bid = blockIdx.x;                     // 0..2047
    int mt  = ((bid >> 9) << 4) + (bid & 15); // 0..63
    int nt  = (bid >> 4) & 31;                // 0..31
    int m0 = mt * TILE_M, n0 = nt * TILE_N;

    const __half* gA = g_Apk + (size_t)mt * NCHUNK * A_CHUNK_H;
    const __half* gB = g_Bpk + (size_t)nt * NCHUNK * B_CHUNK_H;

    if (tid == 0) {
        #pragma unroll
        for (int s = 0; s < NSTAGE; s++) {
            MBARRIER_INIT(mbF[s], 1);
            MBARRIER_INIT(mbE[s], 8);
        }
    }
    __syncthreads();

    // prologue: fill all 3 stages (chunks 0..2)
    if (wid == 0 && elect_one_pred()) {
        #pragma unroll
        for (int s = 0; s < NSTAGE; s++) {
            uint32_t sA = smem + s * STAGE_BYTES;
            MBARRIER_EXPECT_TX(mbF[s], STAGE_BYTES);
            CP_ASYNC_BULK(sA,                 gA + (size_t)s * A_CHUNK_H, A_CHUNK_BYTES, mbF[s]);
            CP_ASYNC_BULK(sA + A_CHUNK_BYTES, gB + (size_t)s * B_CHUNK_H, B_CHUNK_BYTES, mbF[s]);
        }
    }

    // ldmatrix lane-dependent address parts (proven round-8/10/12 mapping)
    int rA_off = ((lane >> 3) & 1) * 8 + (lane & 7);
    int cA_off = lane >> 4;           // 0/1
    int rB_off = (lane >> 4) * 8 + (lane & 7);
    int cB_off = (lane >> 3) & 1;     // 0/1

    uint32_t aRow[4], aXor[4], bRow[2], bXor[2];
    #pragma unroll
    for (int mi = 0; mi < 4; mi++) {
        int r = wm + mi * 16 + rA_off;
        aRow[mi] = (uint32_t)(r * 128);
        aXor[mi] = (uint32_t)((r & 7) << 4);
    }
    #pragma unroll
    for (int nb = 0; nb < 2; nb++) {
        int c = wn + nb * 16 + rB_off;
        bRow[nb] = (uint32_t)(c * 128);
        bXor[nb] = (uint32_t)((c & 7) << 4);
    }

    float acc[4][4][4];
    #pragma unroll
    for (int a = 0; a < 4; a++)
        #pragma unroll
        for (int b = 0; b < 4; b++)
            #pragma unroll
            for (int c = 0; c < 4; c++) acc[a][b][c] = 0.0f;

    int st = 0, ph = 0;
    #pragma unroll 1
    for (int g = 0; g < NCHUNK; g++) {
        uint32_t sA = smem + st * STAGE_BYTES;
        uint32_t sB = sA + A_CHUNK_BYTES;

        MBARRIER_WAIT_PARITY(mbF[st], ph);

        #pragma unroll
        for (int ks = 0; ks < 4; ks++) {
            uint32_t cA16 = (uint32_t)((2 * ks + cA_off) << 4);
            uint32_t cB16 = (uint32_t)((2 * ks + cB_off) << 4);

            uint32_t bfr[2][4];
            #pragma unroll
            for (int nb = 0; nb < 2; nb++)
                ldsm4(sB + bRow[nb] + (cB16 ^ bXor[nb]), bfr[nb]);

            uint32_t afr[4][4];
            #pragma unroll
            for (int mi = 0; mi < 4; mi++)
                ldsm4(sA + aRow[mi] + (cA16 ^ aXor[mi]), afr[mi]);

            #pragma unroll
            for (int mi = 0; mi < 4; mi++) {
                #pragma unroll
                for (int nb = 0; nb < 2; nb++) {
                    #pragma unroll
                    for (int q = 0; q < 2; q++) {
                        int ni = nb * 2 + q;
                        asm volatile(
                            "mma.sync.aligned.m16n8k16.row.col.f32.f16.f16.f32 "
                            "{%0,%1,%2,%3},{%4,%5,%6,%7},{%8,%9},{%0,%1,%2,%3};"
                            : "+f"(acc[mi][ni][0]), "+f"(acc[mi][ni][1]),
                              "+f"(acc[mi][ni][2]), "+f"(acc[mi][ni][3])
                            : "r"(afr[mi][0]), "r"(afr[mi][1]),
                              "r"(afr[mi][2]), "r"(afr[mi][3]),
                              "r"(bfr[nb][2 * q]), "r"(bfr[nb][2 * q + 1]));
                    }
                }
            }
        }

        // consumer done with this stage: one arrive per warp
        if (elect_one_pred()) MBARRIER_ARRIVE(mbE[st]);

        // producer: refill once all 8 warps have consumed this generation
        int gp = g + NSTAGE;
        if (gp < NCHUNK && wid == 0) {
            if (elect_one_pred()) {
                MBARRIER_WAIT_PARITY(mbE[st], ph);
                FENCE_PROXY_ASYNC();
                MBARRIER_EXPECT_TX(mbF[st], STAGE_BYTES);
                CP_ASYNC_BULK(sA, gA + (size_t)gp * A_CHUNK_H, A_CHUNK_BYTES, mbF[st]);
                CP_ASYNC_BULK(sB, gB + (size_t)gp * B_CHUNK_H, B_CHUNK_BYTES, mbF[st]);
            }
        }

        if (++st == NSTAGE) { st = 0; ph ^= 1; }
    }

    // ---------------- store ----------------
    #pragma unroll
    for (int mi = 0; mi < 4; mi++) {
        int r0 = m0 + wm + mi * 16 + gid;
        #pragma unroll
        for (int nb = 0; nb < 2; nb++) {
            #pragma unroll
            for (int q = 0; q < 2; q++) {
                int ni = nb * 2 + q;
                int c = n0 + wn + nb * 16 + q * 8 + tig * 2;
                *(float2*)(out + (size_t)r0 * OUT_DIM + c) =
                    make_float2(acc[mi][ni][0], acc[mi][ni][1]);
                *(float2*)(out + (size_t)(r0 + 8) * OUT_DIM + c) =
                    make_float2(acc[mi][ni][2], acc[mi][ni][3]);
            }
        }
    }

    __syncthreads();
    if (tid == 0) {
        #pragma unroll
        for (int s = 0; s < NSTAGE; s++) {
            MBARRIER_INVAL(mbF[s]);
            MBARRIER_INVAL(mbE[s]);
        }
    }
}

// ---------------------------------------------------------------------------
// kernel_launch
// inputs: x[f32], qweight[i32], wscales[f32], smooth_factor[f32],
//         proj_down[f32], proj_up[f32]; output: f32 [T, OUT]
// ---------------------------------------------------------------------------
extern "C" void kernel_launch(void* const* d_in, const int* in_sizes, int n_in,
                              void* d_out, int out_size) {
    (void)in_sizes; (void)n_in; (void)out_size;
    const float* x         = (const float*)d_in[0];
    const int*   qweight   = (const int*)d_in[1];
    const float* wscales   = (const float*)d_in[2];
    const float* smooth    = (const float*)d_in[3];
    const float* proj_down = (const float*)d_in[4];
    const float* proj_up   = (const float*)d_in[5];
    float* out = (float*)d_out;

    cudaFuncSetAttribute(k4_main, cudaFuncAttributeMaxDynamicSharedMemorySize,
                         DSMEM_BYTES);

    k1_quant<<<(T_DIM * G_CNT) / 8, 256>>>(x, smooth);
    k2_wdq<<<(OUT_DIM * 512) / 256, 256>>>(qweight, wscales);
    k2_convert<<<(IN_DIM * RANK) / 256, 256>>>(proj_up, proj_down);
    k3_lora<<<MT_CNT * KSPLIT, 256>>>();
    k3b_reduce<<<(T_DIM * RANK) / 256, 256>>>();
    k4_main<<<MT_CNT * NT_CNT, 256, DSMEM_BYTES>>>(out);
}

// round 14
// speedup vs baseline: 1.8927x; 1.0412x over previous
#include <cuda_runtime.h>
#include <cuda_fp16.h>
#include <cstdint>

// Problem constants (fixed by the reference)
#define T_DIM   8192
#define IN_DIM  4096
#define OUT_DIM 4096
#define RANK    32
#define GS      64
#define G_CNT   64
#define NCHUNK  65            // 64 main K-chunks + 1 lora chunk (32 lora + 32 zero)
#define TILE_M  128
#define TILE_N  128
#define MT_CNT  (T_DIM / TILE_M)    // 64
#define NT_CNT  (OUT_DIM / TILE_N)  // 32
#define A_CHUNK_H 8192        // 128 rows * 64 halves
#define B_CHUNK_H 8192        // 128 cols * 64 halves
#define A_CHUNK_BYTES 16384
#define B_CHUNK_BYTES 16384
#define STAGE_BYTES 32768
#define NSTAGE  3
#define DSMEM_BYTES (NSTAGE * STAGE_BYTES)   // 96 KB -> 2 CTAs/SM
#define KSPLIT  32
#define K3_KS   128           // k-span per k3 block

// Fused prep kernel block ranges (k2 first so only k1's tail drains)
#define PREP_B2   ((OUT_DIM * 512) / 256)          // 8192  k2_wdq blocks
#define PREP_B2B  ((IN_DIM * RANK) / 256)          // 512   k2_convert blocks
#define PREP_B1   ((T_DIM * G_CNT) / 8)            // 65536 k1 blocks
#define PREP_GRID (PREP_B2 + PREP_B2B + PREP_B1)

// ---------------------------------------------------------------------------
// Device-global scratch (allocation-free per harness rules)
// Packed, pre-swizzled fp16 operand layouts (128B rows, 16B chunks XOR row&7):
//   g_Apk[mt][chunk][row 0..127][64 halves]
//   g_Bpk[nt][chunk][col 0..127][64 halves]
// ---------------------------------------------------------------------------
__device__ __align__(128) __half g_Apk[(size_t)MT_CNT * NCHUNK * A_CHUNK_H];
__device__ __align__(128) __half g_Bpk[(size_t)NT_CNT * NCHUNK * B_CHUNK_H];
__device__ __align__(128) __half g_xsf16[(size_t)T_DIM * IN_DIM];   // smoothed acts (lora)
__device__ __align__(128) float  g_lapart[KSPLIT][(size_t)T_DIM * RANK];
__device__ __align__(128) __half g_pdT[(size_t)RANK * IN_DIM];      // proj_down^T fp16

// ---------------------------------------------------------------------------
// Helpers (sm_90-level features only: mbarrier + cp.async.bulk + mma.sync)
// ---------------------------------------------------------------------------
__device__ __forceinline__ uint32_t smem_to_u32(const void* p) {
    uint32_t a;
    asm("{ .reg .u64 t; cvta.to.shared.u64 t, %1; cvt.u32.u64 %0, t; }"
        : "=r"(a) : "l"(p));
    return a;
}

__device__ __forceinline__ uint32_t elect_one_pred() {
    uint32_t pred;
    asm volatile(
        "{\n\t.reg .pred p;\n\telect.sync _|p, 0xFFFFFFFF;\n\t"
        "selp.b32 %0, 1, 0, p;\n\t}"
        : "=r"(pred));
    return pred;
}

#define MBARRIER_INIT(mbar, count) \
    asm volatile("mbarrier.init.shared.b64 [%0], %1;" \
        :: "r"((uint32_t)(mbar)), "r"((uint32_t)(count)) : "memory")

#define MBARRIER_INVAL(mbar) \
    asm volatile("mbarrier.inval.shared.b64 [%0];" \
        :: "r"((uint32_t)(mbar)) : "memory")

#define MBARRIER_EXPECT_TX(mbar, bytes) \
    asm volatile("mbarrier.arrive.expect_tx.shared.b64 _, [%0], %1;" \
        :: "r"((uint32_t)(mbar)), "r"((uint32_t)(bytes)) : "memory")

#define MBARRIER_ARRIVE(mbar) \
    asm volatile("mbarrier.arrive.shared.b64 _, [%0];" \
        :: "r"((uint32_t)(mbar)) : "memory")

#define MBARRIER_WAIT_PARITY(mbar, parity) do { \
    uint32_t _mbar = (uint32_t)(mbar); \
    uint32_t _par  = (uint32_t)(parity); \
    uint32_t _done; \
    asm volatile( \
        "{\n\t.reg .pred p;\n\t" \
        "mbarrier.try_wait.parity.acquire.cta.shared::cta.b64 p, [%1], %2;\n\t" \
        "selp.b32 %0, 1, 0, p;\n\t}" \
        : "=r"(_done) : "r"(_mbar), "r"(_par) : "memory"); \
    if (!_done) { \
        asm volatile( \
            "{\n\t.reg .pred P1;\n\t" \
            "WAIT_LOOP_%=:\n\t" \
            "mbarrier.try_wait.parity.acquire.cta.shared::cta.b64 P1, [%0], %1, 0x989680;\n\t" \
            "@P1 bra.uni WAIT_DONE_%=;\n\t" \
            "bra.uni WAIT_LOOP_%=;\n\t" \
            "WAIT_DONE_%=:\n\t}" \
            :: "r"(_mbar), "r"(_par) : "memory"); \
    } \
} while (0)

#define FENCE_PROXY_ASYNC() \
    asm volatile("fence.proxy.async.shared::cta;" ::: "memory")

// 1-D bulk copy GMEM -> SMEM with mbarrier transaction completion (SASS: UBLKCP)
#define CP_ASYNC_BULK(dst_smem, src_gmem, bytes, mbar) \
    asm volatile( \
        "cp.async.bulk.shared::cluster.global.mbarrier::complete_tx::bytes " \
        "[%0], [%1], %2, [%3];" \
        :: "r"((uint32_t)(dst_smem)), "l"(src_gmem), "r"((uint32_t)(bytes)), \
           "r"((uint32_t)(mbar)) : "memory")

__device__ __forceinline__ void ldsm4(uint32_t addr, uint32_t f[4]) {
    asm volatile("ldmatrix.sync.aligned.m8n8.x4.shared.b16 {%0,%1,%2,%3}, [%4];"
                 : "=r"(f[0]), "=r"(f[1]), "=r"(f[2]), "=r"(f[3]) : "r"(addr));
}

// swizzled half-index within a 64-half (128B) row: 16B chunk XOR (row&7)
__device__ __forceinline__ int swz_h(int h, int r) {
    return (((h >> 3) ^ (r & 7)) << 3) | (h & 7);
}

// ---------------------------------------------------------------------------
// Fused prep kernel: k2_wdq blocks first, then k2_convert, then k1 (largest
// tail last). All three parts are independent memory streams.
// ---------------------------------------------------------------------------
__global__ void k_prep(const float* __restrict__ x, const float* __restrict__ smooth,
                       const int* __restrict__ qw, const float* __restrict__ wscales,
                       const float* __restrict__ pu, const float* __restrict__ pd) {
    int b = blockIdx.x;
    int tid = threadIdx.x;

    if (b < PREP_B2) {
        // ---- k2_wdq: wdq = qw * wscale[g][o] into packed+swizzled B ----
        int idx = b * 256 + tid;
        int o   = idx >> 9;
        int rem = idx & 511;
        int c   = rem >> 3;
        int c16 = rem & 7;
        float ws = __ldg(&wscales[(size_t)c * OUT_DIM + o]);

        int k = c * 64 + c16 * 8;
        const int4* qp = (const int4*)(qw + (size_t)o * IN_DIM + k);
        int4 v0 = qp[0], v1 = qp[1];
        __half2 p0 = __floats2half2_rn((float)v0.x * ws, (float)v0.y * ws);
        __half2 p1 = __floats2half2_rn((float)v0.z * ws, (float)v0.w * ws);
        __half2 p2 = __floats2half2_rn((float)v1.x * ws, (float)v1.y * ws);
        __half2 p3 = __floats2half2_rn((float)v1.z * ws, (float)v1.w * ws);
        uint4 w;
        w.x = *(uint32_t*)&p0; w.y = *(uint32_t*)&p1;
        w.z = *(uint32_t*)&p2; w.w = *(uint32_t*)&p3;

        int nt = o >> 7, col = o & 127;
        size_t base = ((size_t)(nt * NCHUNK + c) * 128 + col) * 64;
        int phys16 = c16 ^ (col & 7);
        *(uint4*)(g_Bpk + base + phys16 * 8) = w;
        return;
    }
    if (b < PREP_B2 + PREP_B2B) {
        // ---- k2_convert: proj_down^T fp16; B lora chunk ----
        int idx = (b - PREP_B2) * 256 + tid;
        int rr = idx >> 12;
        int k  = idx & 4095;
        g_pdT[(size_t)rr * IN_DIM + k] = __float2half(pd[(size_t)k * RANK + rr]);

        if (idx < OUT_DIM * 8) {
            int o = idx >> 3, c16 = idx & 7;
            uint4 w;
            if (c16 < 4) {
                const float* src = pu + (size_t)o * RANK + c16 * 8;
                __half2 p0 = __floats2half2_rn(src[0], src[1]);
                __half2 p1 = __floats2half2_rn(src[2], src[3]);
                __half2 p2 = __floats2half2_rn(src[4], src[5]);
                __half2 p3 = __floats2half2_rn(src[6], src[7]);
                w.x = *(uint32_t*)&p0; w.y = *(uint32_t*)&p1;
                w.z = *(uint32_t*)&p2; w.w = *(uint32_t*)&p3;
            } else {
                w = make_uint4(0, 0, 0, 0);
            }
            int nt = o >> 7, col = o & 127;
            size_t base = ((size_t)(nt * NCHUNK + 64) * 128 + col) * 64;
            int phys16 = c16 ^ (col & 7);
            *(uint4*)(g_Bpk + base + phys16 * 8) = w;
        }
        return;
    }

    // ---- k1: smooth + per-(token,group) int4 quantization ----
    int warp = (b - PREP_B2 - PREP_B2B) * 8 + (tid >> 5);
    int lane = tid & 31;
    int t = warp >> 6;
    int g = warp & 63;
    int base = g * GS;
    size_t xoff = (size_t)t * IN_DIM + base;

    float xs0 = __fdividef(x[xoff + lane],      smooth[base + lane]);
    float xs1 = __fdividef(x[xoff + lane + 32], smooth[base + lane + 32]);

    g_xsf16[xoff + lane]      = __float2half(xs0);
    g_xsf16[xoff + lane + 32] = __float2half(xs1);

    float m = fmaxf(fabsf(xs0), fabsf(xs1));
    #pragma unroll
    for (int o = 16; o > 0; o >>= 1)
        m = fmaxf(m, __shfl_xor_sync(0xffffffffu, m, o));

    float ascale = m / 7.0f;                 // matches reference amax/7.0
    if (ascale == 0.0f) ascale = 1.0f;       // matches jnp.where

    float q0 = fminf(fmaxf(rintf(xs0 / ascale), -8.0f), 7.0f);
    float q1 = fminf(fmaxf(rintf(xs1 / ascale), -8.0f), 7.0f);

    int mt = t >> 7, r = t & 127;
    size_t pkbase = ((size_t)(mt * NCHUNK + g) * 128 + r) * 64;
    g_Apk[pkbase + swz_h(lane, r)]      = __float2half(q0 * ascale);
    g_Apk[pkbase + swz_h(lane + 32, r)] = __float2half(q1 * ascale);
}

// ---------------------------------------------------------------------------
// K3: lora partials, split-K x32, pdT slice staged in smem.
// Bank mapping: word = c*68 + ks*8 + tig, c = ni*8+gid -> bank = 4*gid+tig+...
// unique per lane -> conflict-free.
// ---------------------------------------------------------------------------
#define PD_STRIDE 136   // halves (68 words)
__global__ void k3_lora() {
    __shared__ __align__(16) __half s_pd[RANK * PD_STRIDE];

    int tid  = threadIdx.x;
    int warp = tid >> 5;
    int lane = tid & 31;
    int gid  = lane >> 2;
    int tig  = lane & 3;
    int mblk   = blockIdx.x >> 5;    // 0..63
    int kslice = blockIdx.x & 31;    // 0..31
    int m0 = mblk * 128 + warp * 16;
    int k0 = kslice * K3_KS;

    // stage pd^T slice [32 rows x 128 halves] into smem (2x int4 per thread)
    {
        int r   = tid >> 3;          // 0..31
        int seg = (tid & 7) * 16;    // halves
        const int4* src = (const int4*)(g_pdT + (size_t)r * IN_DIM + k0 + seg);
        int4* dst = (int4*)(s_pd + r * PD_STRIDE + seg);
        dst[0] = src[0];
        dst[1] = src[1];
    }
    __syncthreads();

    float acc[4][4];
    #pragma unroll
    for (int ni = 0; ni < 4; ni++)
        #pragma unroll
        for (int j = 0; j < 4; j++) acc[ni][j] = 0.0f;

    const uint32_t* xsr0 = (const uint32_t*)(g_xsf16 + (size_t)(m0 + gid) * IN_DIM + k0);
    const uint32_t* xsr1 = (const uint32_t*)(g_xsf16 + (size_t)(m0 + gid + 8) * IN_DIM + k0);

    #pragma unroll
    for (int ks = 0; ks < K3_KS / 16; ks++) {
        int kb = ks * 8 + tig;
        uint32_t a0 = xsr0[kb];
        uint32_t a1 = xsr1[kb];
        uint32_t a2 = xsr0[kb + 4];
        uint32_t a3 = xsr1[kb + 4];
        #pragma unroll
        for (int ni = 0; ni < 4; ni++) {
            int c = ni * 8 + gid;
            const __half* bp = s_pd + c * PD_STRIDE + ks * 16;
            uint32_t b0 = *(const uint32_t*)(bp + tig * 2);
            uint32_t b1 = *(const uint32_t*)(bp + 8 + tig * 2);
            asm volatile(
                "mma.sync.aligned.m16n8k16.row.col.f32.f16.f16.f32 "
                "{%0,%1,%2,%3},{%4,%5,%6,%7},{%8,%9},{%0,%1,%2,%3};"
                : "+f"(acc[ni][0]), "+f"(acc[ni][1]), "+f"(acc[ni][2]), "+f"(acc[ni][3])
                : "r"(a0), "r"(a1), "r"(a2), "r"(a3), "r"(b0), "r"(b1));
        }
    }

    float* dst = g_lapart[kslice];
    #pragma unroll
    for (int ni = 0; ni < 4; ni++) {
        int col = ni * 8 + tig * 2;
        *(float2*)(dst + (size_t)(m0 + gid) * RANK + col)     = make_float2(acc[ni][0], acc[ni][1]);
        *(float2*)(dst + (size_t)(m0 + gid + 8) * RANK + col) = make_float2(acc[ni][2], acc[ni][3]);
    }
}

// K3b: reduce partials -> A lora chunk (fp16) + zero pad
__global__ void k3b_reduce() {
    int idx = blockIdx.x * blockDim.x + threadIdx.x;   // over T*RANK
    float s = 0.0f;
    #pragma unroll
    for (int i = 0; i < KSPLIT; i++) s += g_lapart[i][idx];
    int t = idx >> 5, rk = idx & 31;
    int mt = t >> 7, r = t & 127;
    size_t base = ((size_t)(mt * NCHUNK + 64) * 128 + r) * 64;
    g_Apk[base + swz_h(rk, r)]      = __float2half(s);
    g_Apk[base + swz_h(rk + 32, r)] = __float2half(0.0f);
}

// ---------------------------------------------------------------------------
// K4: fp16 HMMA GEMM, tile 128x128, 65 K-chunks, 2 CTAs/SM, 3-stage
// cp.async.bulk pipeline with full (tx) + empty (count=8) mbarrier ring.
// ---------------------------------------------------------------------------
__global__ void __launch_bounds__(256, 2)
k4_main(float* __restrict__ out) {
    extern __shared__ __align__(128) char dsm[];
    __shared__ __align__(8) unsigned long long s_full[NSTAGE];
    __shared__ __align__(8) unsigned long long s_empty[NSTAGE];

    int tid  = threadIdx.x;
    int wid  = tid >> 5;
    int lane = tid & 31;
    int gid  = lane >> 2;
    int tig  = lane & 3;
    int wm   = (wid >> 2) * 64;     // warp row offset: 0 or 64
    int wn   = (wid & 3) * 32;      // warp col offset: 0,32,64,96

    uint32_t smem = smem_to_u32(dsm);
    uint32_t mbF[NSTAGE], mbE[NSTAGE];
    #pragma unroll
    for (int s = 0; s < NSTAGE; s++) {
        mbF[s] = smem_to_u32(&s_full[s]);
        mbE[s] = smem_to_u32(&s_empty[s]);
    }

    // L2-friendly swizzle: 16-mt chunks sweep all 32 nt (~50MB working set)
    int bid = blockIdx.x;                     // 0..2047
    int mt  = ((bid >> 9) << 4) + (bid & 15); // 0..63
    int nt  = (bid >> 4) & 31;                // 0..31
    int m0 = mt * TILE_M, n0 = nt * TILE_N;

    const __half* gA = g_Apk + (size_t)mt * NCHUNK * A_CHUNK_H;
    const __half* gB = g_Bpk + (size_t)nt * NCHUNK * B_CHUNK_H;

    if (tid == 0) {
        #pragma unroll
        for (int s = 0; s < NSTAGE; s++) {
            MBARRIER_INIT(mbF[s], 1);
            MBARRIER_INIT(mbE[s], 8);
        }
    }
    __syncthreads();

    bool leader = elect_one_pred() != 0;      // hoisted out of the mainloop

    // prologue: fill all 3 stages (chunks 0..2)
    if (wid == 0 && leader) {
        #pragma unroll
        for (int s = 0; s < NSTAGE; s++) {
            uint32_t sA = smem + s * STAGE_BYTES;
            MBARRIER_EXPECT_TX(mbF[s], STAGE_BYTES);
            CP_ASYNC_BULK(sA,                 gA + (size_t)s * A_CHUNK_H, A_CHUNK_BYTES, mbF[s]);
            CP_ASYNC_BULK(sA + A_CHUNK_BYTES, gB + (size_t)s * B_CHUNK_H, B_CHUNK_BYTES, mbF[s]);
        }
    }

    // ldmatrix lane-dependent address parts (proven round-8/10/12 mapping)
    int rA_off = ((lane >> 3) & 1) * 8 + (lane & 7);
    int cA_off = lane >> 4;           // 0/1
    int rB_off = (lane >> 4) * 8 + (lane & 7);
    int cB_off = (lane >> 3) & 1;     // 0/1

    uint32_t aRow[4], aXor[4], bRow[2], bXor[2];
    #pragma unroll
    for (int mi = 0; mi < 4; mi++) {
        int r = wm + mi * 16 + rA_off;
        aRow[mi] = (uint32_t)(r * 128);
        aXor[mi] = (uint32_t)((r & 7) << 4);
    }
    #pragma unroll
    for (int nb = 0; nb < 2; nb++) {
        int c = wn + nb * 16 + rB_off;
        bRow[nb] = (uint32_t)(c * 128);
        bXor[nb] = (uint32_t)((c & 7) << 4);
    }

    float acc[4][4][4];
    #pragma unroll
    for (int a = 0; a < 4; a++)
        #pragma unroll
        for (int b = 0; b < 4; b++)
            #pragma unroll
            for (int c = 0; c < 4; c++) acc[a][b][c] = 0.0f;

    int st = 0, ph = 0;
    #pragma unroll 1
    for (int g = 0; g < NCHUNK; g++) {
        uint32_t sA = smem + st * STAGE_BYTES;
        uint32_t sB = sA + A_CHUNK_BYTES;

        MBARRIER_WAIT_PARITY(mbF[st], ph);

        #pragma unroll
        for (int ks = 0; ks < 4; ks++) {
            uint32_t cA16 = (uint32_t)((2 * ks + cA_off) << 4);
            uint32_t cB16 = (uint32_t)((2 * ks + cB_off) << 4);

            uint32_t bfr[2][4];
            #pragma unroll
            for (int nb = 0; nb < 2; nb++)
                ldsm4(sB + bRow[nb] + (cB16 ^ bXor[nb]), bfr[nb]);

            uint32_t afr[4][4];
            #pragma unroll
            for (int mi = 0; mi < 4; mi++)
                ldsm4(sA + aRow[mi] + (cA16 ^ aXor[mi]), afr[mi]);

            #pragma unroll
            for (int mi = 0; mi < 4; mi++) {
                #pragma unroll
                for (int nb = 0; nb < 2; nb++) {
                    #pragma unroll
                    for (int q = 0; q < 2; q++) {
                        int ni = nb * 2 + q;
                        asm volatile(
                            "mma.sync.aligned.m16n8k16.row.col.f32.f16.f16.f32 "
                            "{%0,%1,%2,%3},{%4,%5,%6,%7},{%8,%9},{%0,%1,%2,%3};"
                            : "+f"(acc[mi][ni][0]), "+f"(acc[mi][ni][1]),
                              "+f"(acc[mi][ni][2]), "+f"(acc[mi][ni][3])
                            : "r"(afr[mi][0]), "r"(afr[mi][1]),
                              "r"(afr[mi][2]), "r"(afr[mi][3]),
                              "r"(bfr[nb][2 * q]), "r"(bfr[nb][2 * q + 1]));
                    }
                }
            }
        }

        // consumer done with this stage: one arrive per warp
        if (leader) MBARRIER_ARRIVE(mbE[st]);

        // producer: refill once all 8 warps have consumed this generation
        int gp = g + NSTAGE;
        if (gp < NCHUNK && wid == 0 && leader) {
            MBARRIER_WAIT_PARITY(mbE[st], ph);
            FENCE_PROXY_ASYNC();
            MBARRIER_EXPECT_TX(mbF[st], STAGE_BYTES);
            CP_ASYNC_BULK(sA, gA + (size_t)gp * A_CHUNK_H, A_CHUNK_BYTES, mbF[st]);
            CP_ASYNC_BULK(sB, gB + (size_t)gp * B_CHUNK_H, B_CHUNK_BYTES, mbF[st]);
        }

        if (++st == NSTAGE) { st = 0; ph ^= 1; }
    }

    // ---------------- store ----------------
    #pragma unroll
    for (int mi = 0; mi < 4; mi++) {
        int r0 = m0 + wm + mi * 16 + gid;
        #pragma unroll
        for (int nb = 0; nb < 2; nb++) {
            #pragma unroll
            for (int q = 0; q < 2; q++) {
                int ni = nb * 2 + q;
                int c = n0 + wn + nb * 16 + q * 8 + tig * 2;
                *(float2*)(out + (size_t)r0 * OUT_DIM + c) =
                    make_float2(acc[mi][ni][0], acc[mi][ni][1]);
                *(float2*)(out + (size_t)(r0 + 8) * OUT_DIM + c) =
                    make_float2(acc[mi][ni][2], acc[mi][ni][3]);
            }
        }
    }

    __syncthreads();
    if (tid == 0) {
        #pragma unroll
        for (int s = 0; s < NSTAGE; s++) {
            MBARRIER_INVAL(mbF[s]);
            MBARRIER_INVAL(mbE[s]);
        }
    }
}

// ---------------------------------------------------------------------------
// kernel_launch
// inputs: x[f32], qweight[i32], wscales[f32], smooth_factor[f32],
//         proj_down[f32], proj_up[f32]; output: f32 [T, OUT]
// ---------------------------------------------------------------------------
extern "C" void kernel_launch(void* const* d_in, const int* in_sizes, int n_in,
                              void* d_out, int out_size) {
    (void)in_sizes; (void)n_in; (void)out_size;
    const float* x         = (const float*)d_in[0];
    const int*   qweight   = (const int*)d_in[1];
    const float* wscales   = (const float*)d_in[2];
    const float* smooth    = (const float*)d_in[3];
    const float* proj_down = (const float*)d_in[4];
    const float* proj_up   = (const float*)d_in[5];
    float* out = (float*)d_out;

    cudaFuncSetAttribute(k4_main, cudaFuncAttributeMaxDynamicSharedMemorySize,
                         DSMEM_BYTES);

    k_prep<<<PREP_GRID, 256>>>(x, smooth, qweight, wscales, proj_up, proj_down);
    k3_lora<<<MT_CNT * KSPLIT, 256>>>();
    k3b_reduce<<<(T_DIM * RANK) / 256, 256>>>();
    k4_main<<<MT_CNT * NT_CNT, 256, DSMEM_BYTES>>>(out);
}